// round 7
// baseline (speedup 1.0000x reference)
#include <cuda_runtime.h>
#include <cstdint>

// Embedding gather: out[i, :] = table[indices[i], :]
// indices: int32[4194304], table: float32[1000000, 16], out: float32[4194304, 16]
//
// R6 finding: L2 evict_last pinning does NOT work on this part (two attempts,
// zero delta in table re-fetch). The real limiter is MLP: each thread had a
// serialized idx->table chain (~1 outstanding miss). Fix: 4-way grid-stride
// batching — 4 independent index loads, then 4 independent 256-bit table
// loads, then streaming stores. Quadruples outstanding misses per thread,
// pushing random-read DRAM utilization up.
//
// 2 threads per row: each handles a 32 B half-row via one v8 load, so a row
// gather is one contiguous 64 B transaction and stores are coalesced.

struct __align__(32) f8 { float4 a, b; };

__device__ __forceinline__ f8 ldg_nc_f8(const f8* p) {
    f8 v;
    asm volatile(
        "ld.global.nc.v8.f32 {%0,%1,%2,%3,%4,%5,%6,%7}, [%8];"
        : "=f"(v.a.x), "=f"(v.a.y), "=f"(v.a.z), "=f"(v.a.w),
          "=f"(v.b.x), "=f"(v.b.y), "=f"(v.b.z), "=f"(v.b.w)
        : "l"(p));
    return v;
}

static constexpr int ROW_HALVES = 2;   // 16 floats = 2 x 32 B halves per row
static constexpr int UNROLL     = 4;

__global__ void __launch_bounds__(256) gather_kernel(
    const int* __restrict__ indices,
    const f8* __restrict__ table8,     // table as 32 B chunks: 2 per row
    float4* __restrict__ out4,
    int total_chunks)
{
    int stride = gridDim.x * blockDim.x;
    int j0 = blockIdx.x * blockDim.x + threadIdx.x;

    // Fast path: all UNROLL chunks in-bounds (grid is sized so this holds for
    // the exact problem size; guard handles any other size).
    if (j0 + (UNROLL - 1) * stride < total_chunks) {
        int j[UNROLL];
#pragma unroll
        for (int u = 0; u < UNROLL; u++) j[u] = j0 + u * stride;

        // Phase 1: all index loads in flight (independent).
        int idx[UNROLL];
#pragma unroll
        for (int u = 0; u < UNROLL; u++) idx[u] = __ldcs(&indices[j[u] >> 1]);

        // Phase 2: all table loads in flight (independent).
        f8 v[UNROLL];
#pragma unroll
        for (int u = 0; u < UNROLL; u++)
            v[u] = ldg_nc_f8(&table8[(long long)idx[u] * ROW_HALVES + (j[u] & 1)]);

        // Phase 3: streaming stores (write-once, don't pollute L2).
#pragma unroll
        for (int u = 0; u < UNROLL; u++) {
            __stcs(&out4[j[u] * 2 + 0], v[u].a);
            __stcs(&out4[j[u] * 2 + 1], v[u].b);
        }
    } else {
        for (int j = j0; j < total_chunks; j += stride) {
            int idx = __ldcs(&indices[j >> 1]);
            f8 v = ldg_nc_f8(&table8[(long long)idx * ROW_HALVES + (j & 1)]);
            __stcs(&out4[j * 2 + 0], v.a);
            __stcs(&out4[j * 2 + 1], v.b);
        }
    }
}

extern "C" void kernel_launch(void* const* d_in, const int* in_sizes, int n_in,
                              void* d_out, int out_size)
{
    // Resolve input order by size: indices = 4,194,304 elems, table = 16,000,000.
    int idx_slot = 0, tab_slot = 1;
    if (n_in >= 2 && in_sizes[0] > in_sizes[1]) { idx_slot = 1; tab_slot = 0; }

    const int* indices = (const int*)d_in[idx_slot];
    const f8*  table8  = (const f8*)d_in[tab_slot];
    float4*    out4    = (float4*)d_out;

    int num_indices  = in_sizes[idx_slot];
    int total_chunks = num_indices * ROW_HALVES;     // 8,388,608

    int threads = 256;
    // Each thread covers UNROLL chunks: grid = total / (threads * UNROLL).
    int blocks = (total_chunks + threads * UNROLL - 1) / (threads * UNROLL);
    gather_kernel<<<blocks, threads>>>(indices, table8, out4, total_chunks);
}